// round 8
// baseline (speedup 1.0000x reference)
#include <cuda_runtime.h>
#include <math.h>
#include <stdint.h>

#define B_  16
#define S_  784
#define D_  768
#define H_  12
#define DH_ 64
#define M_  (B_ * S_)          // 12544

// ---------------- scratch (device globals: allocation-free) ----------------
__device__ float g_q [B_ * S_ * D_];
__device__ float g_k [B_ * S_ * D_];
__device__ float g_v [B_ * S_ * D_];
__device__ float g_ao[B_ * S_ * D_];

__device__ __forceinline__ float to_tf32(float x) {
    uint32_t u;
    asm("cvt.rna.tf32.f32 %0, %1;" : "=r"(u) : "f"(x));
    return __uint_as_float(u);
}
__device__ __forceinline__ uint32_t frag_tf32(float x) {
    uint32_t u;
    asm("cvt.rna.tf32.f32 %0, %1;" : "=r"(u) : "f"(x));
    return u;
}

__device__ __forceinline__ void cp_async16(void* dst, const void* src) {
    uint32_t d = (uint32_t)__cvta_generic_to_shared(dst);
    asm volatile("cp.async.cg.shared.global [%0], [%1], 16;\n" :: "r"(d), "l"(src));
}
#define CP_COMMIT() asm volatile("cp.async.commit_group;\n" ::: "memory")
#define CP_WAIT1()  asm volatile("cp.async.wait_group 1;\n" ::: "memory")

// =====================================================================
// GEMM v2: C[M,N] = A[M,K] @ W[N,K]^T + bias  (+ optional fused RoPE)
// Block 128x128, K-tile 32, 8 warps (4m x 2n), warp tile 32x64.
// cp.async double-buffered staging (raw fp32); RNA tf32 cvt at frag load.
// =====================================================================
#define GTBM 128
#define GTBN 128
#define GTBK 32
#define GPAD 36
#define GBUF (GTBM * GPAD)        // floats per tile buffer (4608)
#define GNK  (D_ / GTBK)          // 24 k-tiles
#define GEMM_SMEM (4 * GBUF * (int)sizeof(float))  // 73728 B

__global__ void __launch_bounds__(256)
gemm_v2_kernel(const float* __restrict__ A, const float* __restrict__ W,
               const float* __restrict__ bias, const float* __restrict__ rope,
               float* __restrict__ C, int do_rope)
{
    extern __shared__ float sm[];
    float* Abuf = sm;               // [2][GBUF]
    float* Wbuf = sm + 2 * GBUF;    // [2][GBUF]

    const int tid  = threadIdx.x;
    const int lane = tid & 31;
    const int warp = tid >> 5;
    const int wm   = (warp >> 1) * 32;   // 0,32,64,96
    const int wn   = (warp & 1)  * 64;   // 0,64
    const int bm   = blockIdx.y * GTBM;
    const int bn   = blockIdx.x * GTBN;
    const int g    = lane >> 2;
    const int t    = lane & 3;

    const float* Ap = A + (size_t)bm * D_;
    const float* Wp = W + (size_t)bn * D_;

    float acc[2][8][4];
#pragma unroll
    for (int mt = 0; mt < 2; mt++)
#pragma unroll
        for (int nt = 0; nt < 8; nt++)
#pragma unroll
            for (int r = 0; r < 4; r++) acc[mt][nt][r] = 0.0f;

    // ---- prologue: stage k-tile 0 into buffer 0 ----
#pragma unroll
    for (int it = 0; it < 4; it++) {
        int f = tid + it * 256;
        int rr = f >> 3;
        int kk = (f & 7) * 4;
        cp_async16(&Abuf[rr * GPAD + kk], Ap + (size_t)rr * D_ + kk);
    }
#pragma unroll
    for (int it = 0; it < 4; it++) {
        int f = tid + it * 256;
        int rr = f >> 3;
        int kk = (f & 7) * 4;
        cp_async16(&Wbuf[rr * GPAD + kk], Wp + (size_t)rr * D_ + kk);
    }
    CP_COMMIT();

    for (int kt = 0; kt < GNK; kt++) {
        const int buf = kt & 1;
        // ---- stage next tile into other buffer ----
        if (kt + 1 < GNK) {
            const int k0n = (kt + 1) * GTBK;
            float* An = Abuf + (buf ^ 1) * GBUF;
            float* Wn = Wbuf + (buf ^ 1) * GBUF;
#pragma unroll
            for (int it = 0; it < 4; it++) {
                int f = tid + it * 256;
                int rr = f >> 3;
                int kk = (f & 7) * 4;
                cp_async16(&An[rr * GPAD + kk], Ap + (size_t)rr * D_ + k0n + kk);
            }
#pragma unroll
            for (int it = 0; it < 4; it++) {
                int f = tid + it * 256;
                int rr = f >> 3;
                int kk = (f & 7) * 4;
                cp_async16(&Wn[rr * GPAD + kk], Wp + (size_t)rr * D_ + k0n + kk);
            }
        }
        CP_COMMIT();
        CP_WAIT1();
        __syncthreads();

        const float* Ab = Abuf + buf * GBUF;
        const float* Wb = Wbuf + buf * GBUF;

#pragma unroll
        for (int kc = 0; kc < 4; kc++) {
            const int kk = kc * 8;
            uint32_t a[2][4];
#pragma unroll
            for (int mt = 0; mt < 2; mt++) {
                int r0 = wm + mt * 16 + g;
                a[mt][0] = frag_tf32(Ab[(r0    ) * GPAD + kk + t    ]);
                a[mt][1] = frag_tf32(Ab[(r0 + 8) * GPAD + kk + t    ]);
                a[mt][2] = frag_tf32(Ab[(r0    ) * GPAD + kk + t + 4]);
                a[mt][3] = frag_tf32(Ab[(r0 + 8) * GPAD + kk + t + 4]);
            }
#pragma unroll
            for (int nt = 0; nt < 8; nt++) {
                int n0 = wn + nt * 8 + g;
                uint32_t b0 = frag_tf32(Wb[n0 * GPAD + kk + t    ]);
                uint32_t b1 = frag_tf32(Wb[n0 * GPAD + kk + t + 4]);
#pragma unroll
                for (int mt = 0; mt < 2; mt++) {
                    asm volatile(
                        "mma.sync.aligned.m16n8k8.row.col.f32.tf32.tf32.f32 "
                        "{%0,%1,%2,%3}, {%4,%5,%6,%7}, {%8,%9}, {%0,%1,%2,%3};"
                        : "+f"(acc[mt][nt][0]), "+f"(acc[mt][nt][1]),
                          "+f"(acc[mt][nt][2]), "+f"(acc[mt][nt][3])
                        : "r"(a[mt][0]), "r"(a[mt][1]), "r"(a[mt][2]), "r"(a[mt][3]),
                          "r"(b0), "r"(b1));
                }
            }
        }
        __syncthreads();
    }

    // ---- epilogue: bias (+ RoPE) + store ----
#pragma unroll
    for (int mt = 0; mt < 2; mt++) {
        int row0 = bm + wm + mt * 16 + g;
#pragma unroll
        for (int nt = 0; nt < 8; nt++) {
            int col = bn + wn + nt * 8 + t * 2;
            float2 bb = *(const float2*)(bias + col);
            float x0 = acc[mt][nt][0] + bb.x;
            float y0 = acc[mt][nt][1] + bb.y;
            float x1 = acc[mt][nt][2] + bb.x;
            float y1 = acc[mt][nt][3] + bb.y;
            if (do_rope) {
                int dh = col & (DH_ - 1);
                float2 a0 = *(const float2*)(rope + (size_t)row0 * DH_ + dh);
                float2 a1 = *(const float2*)(rope + (size_t)(row0 + 8) * DH_ + dh);
                float c0, s0, c1, s1;
                __sincosf(a0.x, &s0, &c0);
                __sincosf(a0.y, &s1, &c1);
                float nx0 = x0 * c0 - y0 * s0;
                float ny0 = y0 * c1 + x0 * s1;
                __sincosf(a1.x, &s0, &c0);
                __sincosf(a1.y, &s1, &c1);
                float nx1 = x1 * c0 - y1 * s0;
                float ny1 = y1 * c1 + x1 * s1;
                x0 = nx0; y0 = ny0; x1 = nx1; y1 = ny1;
            }
            *(float2*)(C + (size_t)row0 * D_ + col)       = make_float2(x0, y0);
            *(float2*)(C + (size_t)(row0 + 8) * D_ + col) = make_float2(x1, y1);
        }
    }
}

// =====================================================================
// Tensor-core flash attention v2: BQ=128, 4 warps, warp tile m32 x n64.
// B-fragments (K/V) amortized over 32 q rows -> LDS/HMMA 1.5.
// =====================================================================
#define APAD 72
#define ABQ  128
#define NQT  ((S_ + ABQ - 1) / ABQ)   // 7
#define NKT  ((S_ + 63) / 64)         // 13
#define ATTN_SMEM ((ABQ + 64 + 64 + ABQ) * APAD * (int)sizeof(float))  // 110592

__global__ void __launch_bounds__(128)
attn_mma_kernel(const float* __restrict__ Q, const float* __restrict__ K,
                const float* __restrict__ V, float* __restrict__ O)
{
    extern __shared__ float smem[];
    float* Qs = smem;                   // [ABQ][APAD]
    float* Ks = Qs + ABQ * APAD;        // [64][APAD]
    float* Vs = Ks + 64 * APAD;         // [64][APAD]
    float* Ps = Vs + 64 * APAD;         // [ABQ][APAD]

    const int tid  = threadIdx.x;
    const int lane = tid & 31;
    const int warp = tid >> 5;
    const int g    = lane >> 2;
    const int t    = lane & 3;
    const int wr   = warp * 32;     // warp q-row base (m32)

    const int q0 = blockIdx.x * ABQ;
    const int h  = blockIdx.y;
    const int b  = blockIdx.z;

    const float* Qb = Q + (size_t)b * S_ * D_ + h * DH_;
    const float* Kb = K + (size_t)b * S_ * D_ + h * DH_;
    const float* Vb = V + (size_t)b * S_ * D_ + h * DH_;

    // ---- stage Q tile (tf32, RNA) ----
    for (int p = tid; p < ABQ * 16; p += 128) {
        int r = p >> 4, c = (p & 15) * 4;
        int s = q0 + r;
        float4 v = make_float4(0.f, 0.f, 0.f, 0.f);
        if (s < S_) v = *(const float4*)(Qb + (size_t)s * D_ + c);
        Qs[r * APAD + c + 0] = to_tf32(v.x);
        Qs[r * APAD + c + 1] = to_tf32(v.y);
        Qs[r * APAD + c + 2] = to_tf32(v.z);
        Qs[r * APAD + c + 3] = to_tf32(v.w);
    }

    float o_acc[2][8][4];
#pragma unroll
    for (int mt = 0; mt < 2; mt++)
#pragma unroll
        for (int nt = 0; nt < 8; nt++)
#pragma unroll
            for (int r = 0; r < 4; r++) o_acc[mt][nt][r] = 0.f;
    float m_prev[2][2] = {{-1e30f, -1e30f}, {-1e30f, -1e30f}};
    float lsum[2][2]   = {{0.f, 0.f}, {0.f, 0.f}};

    const float scale = 0.125f;

    for (int kt = 0; kt < NKT; kt++) {
        const int k0 = kt * 64;

        // ---- stage K, V tiles (tf32, RNA) ----
        for (int p = tid; p < 64 * 16; p += 128) {
            int r = p >> 4, c = (p & 15) * 4;
            int s = k0 + r;
            float4 kv = make_float4(0.f, 0.f, 0.f, 0.f);
            float4 vv = make_float4(0.f, 0.f, 0.f, 0.f);
            if (s < S_) {
                kv = *(const float4*)(Kb + (size_t)s * D_ + c);
                vv = *(const float4*)(Vb + (size_t)s * D_ + c);
            }
            Ks[r * APAD + c + 0] = to_tf32(kv.x);
            Ks[r * APAD + c + 1] = to_tf32(kv.y);
            Ks[r * APAD + c + 2] = to_tf32(kv.z);
            Ks[r * APAD + c + 3] = to_tf32(kv.w);
            Vs[r * APAD + c + 0] = to_tf32(vv.x);
            Vs[r * APAD + c + 1] = to_tf32(vv.y);
            Vs[r * APAD + c + 2] = to_tf32(vv.z);
            Vs[r * APAD + c + 3] = to_tf32(vv.w);
        }
        __syncthreads();

        // ---- S = Q K^T  (m32 x n64, k = 64) ----
        float s_acc[2][8][4];
#pragma unroll
        for (int mt = 0; mt < 2; mt++)
#pragma unroll
            for (int nt = 0; nt < 8; nt++)
#pragma unroll
                for (int r = 0; r < 4; r++) s_acc[mt][nt][r] = 0.f;

#pragma unroll
        for (int kc = 0; kc < 8; kc++) {
            const int kk = kc * 8;
            uint32_t a[2][4];
#pragma unroll
            for (int mt = 0; mt < 2; mt++) {
                int r0 = wr + mt * 16 + g;
                a[mt][0] = __float_as_uint(Qs[(r0    ) * APAD + kk + t    ]);
                a[mt][1] = __float_as_uint(Qs[(r0 + 8) * APAD + kk + t    ]);
                a[mt][2] = __float_as_uint(Qs[(r0    ) * APAD + kk + t + 4]);
                a[mt][3] = __float_as_uint(Qs[(r0 + 8) * APAD + kk + t + 4]);
            }
#pragma unroll
            for (int nt = 0; nt < 8; nt++) {
                uint32_t b0 = __float_as_uint(Ks[(nt * 8 + g) * APAD + kk + t    ]);
                uint32_t b1 = __float_as_uint(Ks[(nt * 8 + g) * APAD + kk + t + 4]);
#pragma unroll
                for (int mt = 0; mt < 2; mt++) {
                    asm volatile(
                        "mma.sync.aligned.m16n8k8.row.col.f32.tf32.tf32.f32 "
                        "{%0,%1,%2,%3}, {%4,%5,%6,%7}, {%8,%9}, {%0,%1,%2,%3};"
                        : "+f"(s_acc[mt][nt][0]), "+f"(s_acc[mt][nt][1]),
                          "+f"(s_acc[mt][nt][2]), "+f"(s_acc[mt][nt][3])
                        : "r"(a[mt][0]), "r"(a[mt][1]), "r"(a[mt][2]), "r"(a[mt][3]),
                          "r"(b0), "r"(b1));
                }
            }
        }

        // ---- scale + mask ----
#pragma unroll
        for (int mt = 0; mt < 2; mt++)
#pragma unroll
            for (int nt = 0; nt < 8; nt++) {
                int c0 = k0 + nt * 8 + 2 * t;
#pragma unroll
                for (int r = 0; r < 4; r++) {
                    int col = c0 + (r & 1);
                    s_acc[mt][nt][r] = (col < S_) ? s_acc[mt][nt][r] * scale : -1e30f;
                }
            }

        // ---- online softmax (4 row sets: mt x half) ----
#pragma unroll
        for (int mt = 0; mt < 2; mt++)
#pragma unroll
            for (int half = 0; half < 2; half++) {
                float mx = -1e30f;
#pragma unroll
                for (int nt = 0; nt < 8; nt++) {
                    mx = fmaxf(mx, s_acc[mt][nt][2 * half]);
                    mx = fmaxf(mx, s_acc[mt][nt][2 * half + 1]);
                }
                mx = fmaxf(mx, __shfl_xor_sync(0xffffffffu, mx, 1));
                mx = fmaxf(mx, __shfl_xor_sync(0xffffffffu, mx, 2));

                float mn   = fmaxf(m_prev[mt][half], mx);
                float corr = __expf(m_prev[mt][half] - mn);
                float rs   = 0.f;
#pragma unroll
                for (int nt = 0; nt < 8; nt++) {
                    float p0 = __expf(s_acc[mt][nt][2 * half]     - mn);
                    float p1 = __expf(s_acc[mt][nt][2 * half + 1] - mn);
                    s_acc[mt][nt][2 * half]     = p0;
                    s_acc[mt][nt][2 * half + 1] = p1;
                    rs += p0 + p1;
                }
                rs += __shfl_xor_sync(0xffffffffu, rs, 1);
                rs += __shfl_xor_sync(0xffffffffu, rs, 2);

                lsum[mt][half]   = lsum[mt][half] * corr + rs;
                m_prev[mt][half] = mn;
#pragma unroll
                for (int nt = 0; nt < 8; nt++) {
                    o_acc[mt][nt][2 * half]     *= corr;
                    o_acc[mt][nt][2 * half + 1] *= corr;
                }
            }

        // ---- P -> smem (tf32), own rows only ----
#pragma unroll
        for (int mt = 0; mt < 2; mt++)
#pragma unroll
            for (int nt = 0; nt < 8; nt++) {
                float2 p0, p1;
                p0.x = to_tf32(s_acc[mt][nt][0]);
                p0.y = to_tf32(s_acc[mt][nt][1]);
                p1.x = to_tf32(s_acc[mt][nt][2]);
                p1.y = to_tf32(s_acc[mt][nt][3]);
                *(float2*)&Ps[(wr + mt * 16 + g    ) * APAD + nt * 8 + 2 * t] = p0;
                *(float2*)&Ps[(wr + mt * 16 + g + 8) * APAD + nt * 8 + 2 * t] = p1;
            }
        __syncwarp();

        // ---- O += P V  (m32 x n64(dh), k = 64 seq) ----
#pragma unroll
        for (int kc = 0; kc < 8; kc++) {
            const int kk = kc * 8;
            uint32_t a[2][4];
#pragma unroll
            for (int mt = 0; mt < 2; mt++) {
                int r0 = wr + mt * 16 + g;
                a[mt][0] = __float_as_uint(Ps[(r0    ) * APAD + kk + t    ]);
                a[mt][1] = __float_as_uint(Ps[(r0 + 8) * APAD + kk + t    ]);
                a[mt][2] = __float_as_uint(Ps[(r0    ) * APAD + kk + t + 4]);
                a[mt][3] = __float_as_uint(Ps[(r0 + 8) * APAD + kk + t + 4]);
            }
#pragma unroll
            for (int nt = 0; nt < 8; nt++) {
                uint32_t b0 = __float_as_uint(Vs[(kk + t    ) * APAD + nt * 8 + g]);
                uint32_t b1 = __float_as_uint(Vs[(kk + t + 4) * APAD + nt * 8 + g]);
#pragma unroll
                for (int mt = 0; mt < 2; mt++) {
                    asm volatile(
                        "mma.sync.aligned.m16n8k8.row.col.f32.tf32.tf32.f32 "
                        "{%0,%1,%2,%3}, {%4,%5,%6,%7}, {%8,%9}, {%0,%1,%2,%3};"
                        : "+f"(o_acc[mt][nt][0]), "+f"(o_acc[mt][nt][1]),
                          "+f"(o_acc[mt][nt][2]), "+f"(o_acc[mt][nt][3])
                        : "r"(a[mt][0]), "r"(a[mt][1]), "r"(a[mt][2]), "r"(a[mt][3]),
                          "r"(b0), "r"(b1));
                }
            }
        }
        __syncthreads();
    }

    // ---- normalize + store [B,S,D] ----
#pragma unroll
    for (int mt = 0; mt < 2; mt++) {
        float inv0 = 1.0f / lsum[mt][0];
        float inv1 = 1.0f / lsum[mt][1];
        int r0 = q0 + wr + mt * 16 + g;
        int r1 = r0 + 8;
#pragma unroll
        for (int nt = 0; nt < 8; nt++) {
            int col = h * DH_ + nt * 8 + 2 * t;
            if (r0 < S_) {
                float2 o;
                o.x = o_acc[mt][nt][0] * inv0;
                o.y = o_acc[mt][nt][1] * inv0;
                *(float2*)(O + ((size_t)b * S_ + r0) * D_ + col) = o;
            }
            if (r1 < S_) {
                float2 o;
                o.x = o_acc[mt][nt][2] * inv1;
                o.y = o_acc[mt][nt][3] * inv1;
                *(float2*)(O + ((size_t)b * S_ + r1) * D_ + col) = o;
            }
        }
    }
}

// ---------------- launch ----------------
extern "C" void kernel_launch(void* const* d_in, const int* in_sizes, int n_in,
                              void* d_out, int out_size)
{
    const float* hs   = (const float*)d_in[0];
    const float* rope = (const float*)d_in[1];
    const float* wq   = (const float*)d_in[2];
    const float* bq   = (const float*)d_in[3];
    const float* wk   = (const float*)d_in[4];
    const float* bk   = (const float*)d_in[5];
    const float* wv   = (const float*)d_in[6];
    const float* bv   = (const float*)d_in[7];
    const float* wo   = (const float*)d_in[8];
    const float* bo   = (const float*)d_in[9];
    float* out = (float*)d_out;

    float *gq, *gk, *gv, *gao;
    cudaGetSymbolAddress((void**)&gq,  g_q);
    cudaGetSymbolAddress((void**)&gk,  g_k);
    cudaGetSymbolAddress((void**)&gv,  g_v);
    cudaGetSymbolAddress((void**)&gao, g_ao);

    cudaFuncSetAttribute(attn_mma_kernel,
                         cudaFuncAttributeMaxDynamicSharedMemorySize, ATTN_SMEM);
    cudaFuncSetAttribute(gemm_v2_kernel,
                         cudaFuncAttributeMaxDynamicSharedMemorySize, GEMM_SMEM);

    dim3 gblk(256);
    dim3 ggrid(D_ / GTBN, M_ / GTBM);   // (6, 98)

    gemm_v2_kernel<<<ggrid, gblk, GEMM_SMEM>>>(hs, wq, bq, rope, gq, 1);
    gemm_v2_kernel<<<ggrid, gblk, GEMM_SMEM>>>(hs, wk, bk, rope, gk, 1);
    gemm_v2_kernel<<<ggrid, gblk, GEMM_SMEM>>>(hs, wv, bv, rope, gv, 0);

    dim3 agrid(NQT, H_, B_);            // (7, 12, 16)
    attn_mma_kernel<<<agrid, 128, ATTN_SMEM>>>(gq, gk, gv, gao);

    gemm_v2_kernel<<<ggrid, gblk, GEMM_SMEM>>>(gao, wo, bo, rope, out, 0);
}

// round 11
// speedup vs baseline: 1.1069x; 1.1069x over previous
#include <cuda_runtime.h>
#include <math.h>
#include <stdint.h>

#define B_  16
#define S_  784
#define D_  768
#define H_  12
#define DH_ 64
#define M_  (B_ * S_)          // 12544

// ---------------- scratch (device globals: allocation-free) ----------------
__device__ float g_q [B_ * S_ * D_];
__device__ float g_k [B_ * S_ * D_];
__device__ float g_v [B_ * S_ * D_];
__device__ float g_ao[B_ * S_ * D_];     // rounded hs first, attention output later
__device__ float g_w [4 * D_ * D_];      // rounded weights

__device__ __forceinline__ float to_tf32(float x) {
    uint32_t u;
    asm("cvt.rna.tf32.f32 %0, %1;" : "=r"(u) : "f"(x));
    return __uint_as_float(u);
}

__device__ __forceinline__ void cp_async16(void* dst, const void* src) {
    uint32_t d = (uint32_t)__cvta_generic_to_shared(dst);
    asm volatile("cp.async.cg.shared.global [%0], [%1], 16;\n" :: "r"(d), "l"(src));
}
#define CP_COMMIT() asm volatile("cp.async.commit_group;\n" ::: "memory")
#define CP_WAIT1()  asm volatile("cp.async.wait_group 1;\n" ::: "memory")

// =====================================================================
// RNA tf32 pre-rounding (elementwise, float4)
// =====================================================================
__global__ void __launch_bounds__(256)
round4_kernel(const float* __restrict__ in, float* __restrict__ out, int n4)
{
    int i = blockIdx.x * 256 + threadIdx.x;
    if (i < n4) {
        float4 v = ((const float4*)in)[i];
        float4 o;
        o.x = to_tf32(v.x);
        o.y = to_tf32(v.y);
        o.z = to_tf32(v.z);
        o.w = to_tf32(v.w);
        ((float4*)out)[i] = o;
    }
}

// =====================================================================
// GEMM v3: C[M,N] = A[M,K] @ W[N,K]^T + bias  (+ fused RoPE, + tf32 out)
// A and W are PRE-ROUNDED tf32 values; raw bits feed the MMA.
// Block 128x128, K-tile 32, 8 warps (4m x 2n), warp tile 32x64.
// =====================================================================
#define GTBM 128
#define GTBN 128
#define GTBK 32
#define GPAD 36
#define GBUF (GTBM * GPAD)
#define GNK  (D_ / GTBK)
#define GEMM_SMEM (4 * GBUF * (int)sizeof(float))  // 73728 B

__global__ void __launch_bounds__(256)
gemm_v3_kernel(const float* __restrict__ A, const float* __restrict__ W,
               const float* __restrict__ bias, const float* __restrict__ rope,
               float* __restrict__ C, int do_rope, int round_out)
{
    extern __shared__ float sm[];
    float* Abuf = sm;
    float* Wbuf = sm + 2 * GBUF;

    const int tid  = threadIdx.x;
    const int lane = tid & 31;
    const int warp = tid >> 5;
    const int wm   = (warp >> 1) * 32;
    const int wn   = (warp & 1)  * 64;
    const int bm   = blockIdx.y * GTBM;
    const int bn   = blockIdx.x * GTBN;
    const int g    = lane >> 2;
    const int t    = lane & 3;

    const float* Ap = A + (size_t)bm * D_;
    const float* Wp = W + (size_t)bn * D_;

    float acc[2][8][4];
#pragma unroll
    for (int mt = 0; mt < 2; mt++)
#pragma unroll
        for (int nt = 0; nt < 8; nt++)
#pragma unroll
            for (int r = 0; r < 4; r++) acc[mt][nt][r] = 0.0f;

#pragma unroll
    for (int it = 0; it < 4; it++) {
        int f = tid + it * 256;
        int rr = f >> 3;
        int kk = (f & 7) * 4;
        cp_async16(&Abuf[rr * GPAD + kk], Ap + (size_t)rr * D_ + kk);
    }
#pragma unroll
    for (int it = 0; it < 4; it++) {
        int f = tid + it * 256;
        int rr = f >> 3;
        int kk = (f & 7) * 4;
        cp_async16(&Wbuf[rr * GPAD + kk], Wp + (size_t)rr * D_ + kk);
    }
    CP_COMMIT();

    for (int kt = 0; kt < GNK; kt++) {
        const int buf = kt & 1;
        if (kt + 1 < GNK) {
            const int k0n = (kt + 1) * GTBK;
            float* An = Abuf + (buf ^ 1) * GBUF;
            float* Wn = Wbuf + (buf ^ 1) * GBUF;
#pragma unroll
            for (int it = 0; it < 4; it++) {
                int f = tid + it * 256;
                int rr = f >> 3;
                int kk = (f & 7) * 4;
                cp_async16(&An[rr * GPAD + kk], Ap + (size_t)rr * D_ + k0n + kk);
            }
#pragma unroll
            for (int it = 0; it < 4; it++) {
                int f = tid + it * 256;
                int rr = f >> 3;
                int kk = (f & 7) * 4;
                cp_async16(&Wn[rr * GPAD + kk], Wp + (size_t)rr * D_ + k0n + kk);
            }
        }
        CP_COMMIT();
        CP_WAIT1();
        __syncthreads();

        const float* Ab = Abuf + buf * GBUF;
        const float* Wb = Wbuf + buf * GBUF;

#pragma unroll
        for (int kc = 0; kc < 4; kc++) {
            const int kk = kc * 8;
            uint32_t a[2][4];
#pragma unroll
            for (int mt = 0; mt < 2; mt++) {
                int r0 = wm + mt * 16 + g;
                a[mt][0] = __float_as_uint(Ab[(r0    ) * GPAD + kk + t    ]);
                a[mt][1] = __float_as_uint(Ab[(r0 + 8) * GPAD + kk + t    ]);
                a[mt][2] = __float_as_uint(Ab[(r0    ) * GPAD + kk + t + 4]);
                a[mt][3] = __float_as_uint(Ab[(r0 + 8) * GPAD + kk + t + 4]);
            }
#pragma unroll
            for (int nt = 0; nt < 8; nt++) {
                int n0 = wn + nt * 8 + g;
                uint32_t b0 = __float_as_uint(Wb[n0 * GPAD + kk + t    ]);
                uint32_t b1 = __float_as_uint(Wb[n0 * GPAD + kk + t + 4]);
#pragma unroll
                for (int mt = 0; mt < 2; mt++) {
                    asm volatile(
                        "mma.sync.aligned.m16n8k8.row.col.f32.tf32.tf32.f32 "
                        "{%0,%1,%2,%3}, {%4,%5,%6,%7}, {%8,%9}, {%0,%1,%2,%3};"
                        : "+f"(acc[mt][nt][0]), "+f"(acc[mt][nt][1]),
                          "+f"(acc[mt][nt][2]), "+f"(acc[mt][nt][3])
                        : "r"(a[mt][0]), "r"(a[mt][1]), "r"(a[mt][2]), "r"(a[mt][3]),
                          "r"(b0), "r"(b1));
                }
            }
        }
        __syncthreads();
    }

    // ---- epilogue: bias (+ RoPE) (+ tf32 round) + store ----
#pragma unroll
    for (int mt = 0; mt < 2; mt++) {
        int row0 = bm + wm + mt * 16 + g;
#pragma unroll
        for (int nt = 0; nt < 8; nt++) {
            int col = bn + wn + nt * 8 + t * 2;
            float2 bb = *(const float2*)(bias + col);
            float x0 = acc[mt][nt][0] + bb.x;
            float y0 = acc[mt][nt][1] + bb.y;
            float x1 = acc[mt][nt][2] + bb.x;
            float y1 = acc[mt][nt][3] + bb.y;
            if (do_rope) {
                int dh = col & (DH_ - 1);
                float2 a0 = *(const float2*)(rope + (size_t)row0 * DH_ + dh);
                float2 a1 = *(const float2*)(rope + (size_t)(row0 + 8) * DH_ + dh);
                float c0, s0, c1, s1;
                __sincosf(a0.x, &s0, &c0);
                __sincosf(a0.y, &s1, &c1);
                float nx0 = x0 * c0 - y0 * s0;
                float ny0 = y0 * c1 + x0 * s1;
                __sincosf(a1.x, &s0, &c0);
                __sincosf(a1.y, &s1, &c1);
                float nx1 = x1 * c0 - y1 * s0;
                float ny1 = y1 * c1 + x1 * s1;
                x0 = nx0; y0 = ny0; x1 = nx1; y1 = ny1;
            }
            if (round_out) {
                x0 = to_tf32(x0); y0 = to_tf32(y0);
                x1 = to_tf32(x1); y1 = to_tf32(y1);
            }
            *(float2*)(C + (size_t)row0 * D_ + col)       = make_float2(x0, y0);
            *(float2*)(C + (size_t)(row0 + 8) * D_ + col) = make_float2(x1, y1);
        }
    }
}

// =====================================================================
// Tensor-core flash attention v3: BQ=128, 4 warps, warp tile m32 x n64.
// Q/K/V arrive PRE-ROUNDED tf32 -> cp.async staging, zero cvt.
// Split-barrier K/V prefetch: V load overlaps QK^T, K load overlaps PV.
// Output rounded to tf32 for the final raw-feed GEMM.
// =====================================================================
#define APAD 72
#define ABQ  128
#define NQT  ((S_ + ABQ - 1) / ABQ)   // 7
#define NKT  ((S_ + 63) / 64)         // 13
#define ATTN_SMEM ((ABQ + 64 + 64 + ABQ) * APAD * (int)sizeof(float))  // 110592

__global__ void __launch_bounds__(128)
attn_mma_kernel(const float* __restrict__ Q, const float* __restrict__ K,
                const float* __restrict__ V, float* __restrict__ O)
{
    extern __shared__ float smem[];
    float* Qs = smem;                   // [ABQ][APAD]
    float* Ks = Qs + ABQ * APAD;        // [64][APAD]
    float* Vs = Ks + 64 * APAD;         // [64][APAD]
    float* Ps = Vs + 64 * APAD;         // [ABQ][APAD]

    const int tid  = threadIdx.x;
    const int lane = tid & 31;
    const int warp = tid >> 5;
    const int g    = lane >> 2;
    const int t    = lane & 3;
    const int wr   = warp * 32;

    const int q0 = blockIdx.x * ABQ;
    const int h  = blockIdx.y;
    const int b  = blockIdx.z;

    const float* Qb = Q + (size_t)b * S_ * D_ + h * DH_;
    const float* Kb = K + (size_t)b * S_ * D_ + h * DH_;
    const float* Vb = V + (size_t)b * S_ * D_ + h * DH_;

    // ---- stage Q (cp.async; clamp out-of-range rows to row S_-1: finite, unused) ----
#pragma unroll
    for (int i = 0; i < 16; i++) {
        int f = tid + i * 128;
        int r = f >> 4, c = (f & 15) * 4;
        int s = q0 + r; if (s >= S_) s = S_ - 1;
        cp_async16(&Qs[r * APAD + c], Qb + (size_t)s * D_ + c);
    }
    // stage K[0]; commit group {Q,K0}
#pragma unroll
    for (int i = 0; i < 8; i++) {
        int f = tid + i * 128;
        int r = f >> 4, c = (f & 15) * 4;
        int s = r; if (s >= S_) s = S_ - 1;
        cp_async16(&Ks[r * APAD + c], Kb + (size_t)s * D_ + c);
    }
    CP_COMMIT();
    // stage V[0]; commit group {V0}
#pragma unroll
    for (int i = 0; i < 8; i++) {
        int f = tid + i * 128;
        int r = f >> 4, c = (f & 15) * 4;
        int s = r; if (s >= S_) s = S_ - 1;
        cp_async16(&Vs[r * APAD + c], Vb + (size_t)s * D_ + c);
    }
    CP_COMMIT();

    float o_acc[2][8][4];
#pragma unroll
    for (int mt = 0; mt < 2; mt++)
#pragma unroll
        for (int nt = 0; nt < 8; nt++)
#pragma unroll
            for (int r = 0; r < 4; r++) o_acc[mt][nt][r] = 0.f;
    float m_prev[2][2] = {{-1e30f, -1e30f}, {-1e30f, -1e30f}};
    float lsum[2][2]   = {{0.f, 0.f}, {0.f, 0.f}};

    const float scale = 0.125f;

    for (int kt = 0; kt < NKT; kt++) {
        const int k0 = kt * 64;

        // ---- wait K[kt] (leaves V[kt] group possibly in flight) ----
        CP_WAIT1();
        __syncthreads();

        // ---- S = Q K^T  (m32 x n64, k = 64) ----
        float s_acc[2][8][4];
#pragma unroll
        for (int mt = 0; mt < 2; mt++)
#pragma unroll
            for (int nt = 0; nt < 8; nt++)
#pragma unroll
                for (int r = 0; r < 4; r++) s_acc[mt][nt][r] = 0.f;

#pragma unroll
        for (int kc = 0; kc < 8; kc++) {
            const int kk = kc * 8;
            uint32_t a[2][4];
#pragma unroll
            for (int mt = 0; mt < 2; mt++) {
                int r0 = wr + mt * 16 + g;
                a[mt][0] = __float_as_uint(Qs[(r0    ) * APAD + kk + t    ]);
                a[mt][1] = __float_as_uint(Qs[(r0 + 8) * APAD + kk + t    ]);
                a[mt][2] = __float_as_uint(Qs[(r0    ) * APAD + kk + t + 4]);
                a[mt][3] = __float_as_uint(Qs[(r0 + 8) * APAD + kk + t + 4]);
            }
#pragma unroll
            for (int nt = 0; nt < 8; nt++) {
                uint32_t b0 = __float_as_uint(Ks[(nt * 8 + g) * APAD + kk + t    ]);
                uint32_t b1 = __float_as_uint(Ks[(nt * 8 + g) * APAD + kk + t + 4]);
#pragma unroll
                for (int mt = 0; mt < 2; mt++) {
                    asm volatile(
                        "mma.sync.aligned.m16n8k8.row.col.f32.tf32.tf32.f32 "
                        "{%0,%1,%2,%3}, {%4,%5,%6,%7}, {%8,%9}, {%0,%1,%2,%3};"
                        : "+f"(s_acc[mt][nt][0]), "+f"(s_acc[mt][nt][1]),
                          "+f"(s_acc[mt][nt][2]), "+f"(s_acc[mt][nt][3])
                        : "r"(a[mt][0]), "r"(a[mt][1]), "r"(a[mt][2]), "r"(a[mt][3]),
                          "r"(b0), "r"(b1));
                }
            }
        }
        __syncthreads();   // all warps done reading Ks

        // ---- prefetch K[kt+1] (overlaps softmax + PV) ----
        if (kt + 1 < NKT) {
            const int kn = (kt + 1) * 64;
#pragma unroll
            for (int i = 0; i < 8; i++) {
                int f = tid + i * 128;
                int r = f >> 4, c = (f & 15) * 4;
                int s = kn + r; if (s >= S_) s = S_ - 1;
                cp_async16(&Ks[r * APAD + c], Kb + (size_t)s * D_ + c);
            }
        }
        CP_COMMIT();   // pending: {V[kt]}, {K[kt+1]}

        // ---- scale + mask ----
#pragma unroll
        for (int mt = 0; mt < 2; mt++)
#pragma unroll
            for (int nt = 0; nt < 8; nt++) {
                int c0 = k0 + nt * 8 + 2 * t;
#pragma unroll
                for (int r = 0; r < 4; r++) {
                    int col = c0 + (r & 1);
                    s_acc[mt][nt][r] = (col < S_) ? s_acc[mt][nt][r] * scale : -1e30f;
                }
            }

        // ---- online softmax ----
#pragma unroll
        for (int mt = 0; mt < 2; mt++)
#pragma unroll
            for (int half = 0; half < 2; half++) {
                float mx = -1e30f;
#pragma unroll
                for (int nt = 0; nt < 8; nt++) {
                    mx = fmaxf(mx, s_acc[mt][nt][2 * half]);
                    mx = fmaxf(mx, s_acc[mt][nt][2 * half + 1]);
                }
                mx = fmaxf(mx, __shfl_xor_sync(0xffffffffu, mx, 1));
                mx = fmaxf(mx, __shfl_xor_sync(0xffffffffu, mx, 2));

                float mn   = fmaxf(m_prev[mt][half], mx);
                float corr = __expf(m_prev[mt][half] - mn);
                float rs   = 0.f;
#pragma unroll
                for (int nt = 0; nt < 8; nt++) {
                    float p0 = __expf(s_acc[mt][nt][2 * half]     - mn);
                    float p1 = __expf(s_acc[mt][nt][2 * half + 1] - mn);
                    s_acc[mt][nt][2 * half]     = p0;
                    s_acc[mt][nt][2 * half + 1] = p1;
                    rs += p0 + p1;
                }
                rs += __shfl_xor_sync(0xffffffffu, rs, 1);
                rs += __shfl_xor_sync(0xffffffffu, rs, 2);

                lsum[mt][half]   = lsum[mt][half] * corr + rs;
                m_prev[mt][half] = mn;
#pragma unroll
                for (int nt = 0; nt < 8; nt++) {
                    o_acc[mt][nt][2 * half]     *= corr;
                    o_acc[mt][nt][2 * half + 1] *= corr;
                }
            }

        // ---- wait V[kt] ----
        CP_WAIT1();
        __syncthreads();

        // ---- P -> smem (tf32), warp-private rows ----
#pragma unroll
        for (int mt = 0; mt < 2; mt++)
#pragma unroll
            for (int nt = 0; nt < 8; nt++) {
                float2 p0, p1;
                p0.x = to_tf32(s_acc[mt][nt][0]);
                p0.y = to_tf32(s_acc[mt][nt][1]);
                p1.x = to_tf32(s_acc[mt][nt][2]);
                p1.y = to_tf32(s_acc[mt][nt][3]);
                *(float2*)&Ps[(wr + mt * 16 + g    ) * APAD + nt * 8 + 2 * t] = p0;
                *(float2*)&Ps[(wr + mt * 16 + g + 8) * APAD + nt * 8 + 2 * t] = p1;
            }
        __syncwarp();

        // ---- O += P V ----
#pragma unroll
        for (int kc = 0; kc < 8; kc++) {
            const int kk = kc * 8;
            uint32_t a[2][4];
#pragma unroll
            for (int mt = 0; mt < 2; mt++) {
                int r0 = wr + mt * 16 + g;
                a[mt][0] = __float_as_uint(Ps[(r0    ) * APAD + kk + t    ]);
                a[mt][1] = __float_as_uint(Ps[(r0 + 8) * APAD + kk + t    ]);
                a[mt][2] = __float_as_uint(Ps[(r0    ) * APAD + kk + t + 4]);
                a[mt][3] = __float_as_uint(Ps[(r0 + 8) * APAD + kk + t + 4]);
            }
#pragma unroll
            for (int nt = 0; nt < 8; nt++) {
                uint32_t b0 = __float_as_uint(Vs[(kk + t    ) * APAD + nt * 8 + g]);
                uint32_t b1 = __float_as_uint(Vs[(kk + t + 4) * APAD + nt * 8 + g]);
#pragma unroll
                for (int mt = 0; mt < 2; mt++) {
                    asm volatile(
                        "mma.sync.aligned.m16n8k8.row.col.f32.tf32.tf32.f32 "
                        "{%0,%1,%2,%3}, {%4,%5,%6,%7}, {%8,%9}, {%0,%1,%2,%3};"
                        : "+f"(o_acc[mt][nt][0]), "+f"(o_acc[mt][nt][1]),
                          "+f"(o_acc[mt][nt][2]), "+f"(o_acc[mt][nt][3])
                        : "r"(a[mt][0]), "r"(a[mt][1]), "r"(a[mt][2]), "r"(a[mt][3]),
                          "r"(b0), "r"(b1));
                }
            }
        }
        __syncthreads();   // all warps done reading Vs

        // ---- prefetch V[kt+1] (overlaps next QK^T) ----
        if (kt + 1 < NKT) {
            const int kn = (kt + 1) * 64;
#pragma unroll
            for (int i = 0; i < 8; i++) {
                int f = tid + i * 128;
                int r = f >> 4, c = (f & 15) * 4;
                int s = kn + r; if (s >= S_) s = S_ - 1;
                cp_async16(&Vs[r * APAD + c], Vb + (size_t)s * D_ + c);
            }
        }
        CP_COMMIT();   // pending: {K[kt+1]}, {V[kt+1]}
    }

    // ---- normalize + round + store [B,S,D] ----
#pragma unroll
    for (int mt = 0; mt < 2; mt++) {
        float inv0 = 1.0f / lsum[mt][0];
        float inv1 = 1.0f / lsum[mt][1];
        int r0 = q0 + wr + mt * 16 + g;
        int r1 = r0 + 8;
#pragma unroll
        for (int nt = 0; nt < 8; nt++) {
            int col = h * DH_ + nt * 8 + 2 * t;
            if (r0 < S_) {
                float2 o;
                o.x = to_tf32(o_acc[mt][nt][0] * inv0);
                o.y = to_tf32(o_acc[mt][nt][1] * inv0);
                *(float2*)(O + ((size_t)b * S_ + r0) * D_ + col) = o;
            }
            if (r1 < S_) {
                float2 o;
                o.x = to_tf32(o_acc[mt][nt][2] * inv1);
                o.y = to_tf32(o_acc[mt][nt][3] * inv1);
                *(float2*)(O + ((size_t)b * S_ + r1) * D_ + col) = o;
            }
        }
    }
}

// ---------------- launch ----------------
extern "C" void kernel_launch(void* const* d_in, const int* in_sizes, int n_in,
                              void* d_out, int out_size)
{
    const float* hs   = (const float*)d_in[0];
    const float* rope = (const float*)d_in[1];
    const float* wq   = (const float*)d_in[2];
    const float* bq   = (const float*)d_in[3];
    const float* wk   = (const float*)d_in[4];
    const float* bk   = (const float*)d_in[5];
    const float* wv   = (const float*)d_in[6];
    const float* bv   = (const float*)d_in[7];
    const float* wo   = (const float*)d_in[8];
    const float* bo   = (const float*)d_in[9];
    float* out = (float*)d_out;

    float *gq, *gk, *gv, *gao, *gw;
    cudaGetSymbolAddress((void**)&gq,  g_q);
    cudaGetSymbolAddress((void**)&gk,  g_k);
    cudaGetSymbolAddress((void**)&gv,  g_v);
    cudaGetSymbolAddress((void**)&gao, g_ao);
    cudaGetSymbolAddress((void**)&gw,  g_w);

    cudaFuncSetAttribute(attn_mma_kernel,
                         cudaFuncAttributeMaxDynamicSharedMemorySize, ATTN_SMEM);
    cudaFuncSetAttribute(gemm_v3_kernel,
                         cudaFuncAttributeMaxDynamicSharedMemorySize, GEMM_SMEM);

    // ---- pre-round hs and weights to tf32 (RNA) ----
    const int nhs4 = M_ * D_ / 4;
    const int nw4  = D_ * D_ / 4;
    round4_kernel<<<(nhs4 + 255) / 256, 256>>>(hs, gao, nhs4);
    round4_kernel<<<(nw4  + 255) / 256, 256>>>(wq, gw + 0 * (size_t)D_ * D_, nw4);
    round4_kernel<<<(nw4  + 255) / 256, 256>>>(wk, gw + 1 * (size_t)D_ * D_, nw4);
    round4_kernel<<<(nw4  + 255) / 256, 256>>>(wv, gw + 2 * (size_t)D_ * D_, nw4);
    round4_kernel<<<(nw4  + 255) / 256, 256>>>(wo, gw + 3 * (size_t)D_ * D_, nw4);

    dim3 gblk(256);
    dim3 ggrid(D_ / GTBN, M_ / GTBM);   // (6, 98)

    gemm_v3_kernel<<<ggrid, gblk, GEMM_SMEM>>>(gao, gw + 0 * (size_t)D_ * D_, bq, rope, gq, 1, 1);
    gemm_v3_kernel<<<ggrid, gblk, GEMM_SMEM>>>(gao, gw + 1 * (size_t)D_ * D_, bk, rope, gk, 1, 1);
    gemm_v3_kernel<<<ggrid, gblk, GEMM_SMEM>>>(gao, gw + 2 * (size_t)D_ * D_, bv, rope, gv, 0, 1);

    dim3 agrid(NQT, H_, B_);            // (7, 12, 16)
    attn_mma_kernel<<<agrid, 128, ATTN_SMEM>>>(gq, gk, gv, gao);

    gemm_v3_kernel<<<ggrid, gblk, GEMM_SMEM>>>(gao, gw + 3 * (size_t)D_ * D_, bo, rope, out, 0, 0);
}

// round 15
// speedup vs baseline: 1.1369x; 1.0271x over previous
#include <cuda_runtime.h>
#include <math.h>
#include <stdint.h>

#define B_  16
#define S_  784
#define D_  768
#define H_  12
#define DH_ 64
#define M_  (B_ * S_)          // 12544

// ---------------- scratch (device globals: allocation-free) ----------------
__device__ float g_q [B_ * S_ * D_];
__device__ float g_k [B_ * S_ * D_];
__device__ float g_v [B_ * S_ * D_];
__device__ float g_ao[B_ * S_ * D_];     // rounded hs first, attention output later
__device__ float g_w [4 * D_ * D_];      // rounded weights

__device__ __forceinline__ float to_tf32(float x) {
    uint32_t u;
    asm("cvt.rna.tf32.f32 %0, %1;" : "=r"(u) : "f"(x));
    return __uint_as_float(u);
}

__device__ __forceinline__ void cp_async16(void* dst, const void* src) {
    uint32_t d = (uint32_t)__cvta_generic_to_shared(dst);
    asm volatile("cp.async.cg.shared.global [%0], [%1], 16;\n" :: "r"(d), "l"(src));
}
#define CP_COMMIT() asm volatile("cp.async.commit_group;\n" ::: "memory")
#define CP_WAIT1()  asm volatile("cp.async.wait_group 1;\n" ::: "memory")

// =====================================================================
// RNA tf32 pre-rounding
// =====================================================================
__global__ void __launch_bounds__(256)
round4_kernel(const float* __restrict__ in, float* __restrict__ out, int n4)
{
    int i = blockIdx.x * 256 + threadIdx.x;
    if (i < n4) {
        float4 v = ((const float4*)in)[i];
        float4 o;
        o.x = to_tf32(v.x);
        o.y = to_tf32(v.y);
        o.z = to_tf32(v.z);
        o.w = to_tf32(v.w);
        ((float4*)out)[i] = o;
    }
}

// all 4 weight matrices in one launch
__global__ void __launch_bounds__(256)
round_w_kernel(const float* __restrict__ w0, const float* __restrict__ w1,
               const float* __restrict__ w2, const float* __restrict__ w3,
               float* __restrict__ out, int n4)
{
    int i = blockIdx.x * 256 + threadIdx.x;
    if (i < 4 * n4) {
        int sel = i / n4;
        int j   = i - sel * n4;
        const float* src = (sel == 0) ? w0 : (sel == 1) ? w1 : (sel == 2) ? w2 : w3;
        float4 v = ((const float4*)src)[j];
        float4 o;
        o.x = to_tf32(v.x);
        o.y = to_tf32(v.y);
        o.z = to_tf32(v.z);
        o.w = to_tf32(v.w);
        ((float4*)out)[i] = o;
    }
}

// =====================================================================
// GEMM v4: C[M,N] = A[M,K] @ W[N,K]^T + bias  (+ fused RoPE, + tf32 out)
// A and W PRE-ROUNDED tf32; raw bits feed the MMA.
// Block 256x128, K-tile 32, 8 warps (2m x 2n... -> 4m x 2n of 64x64),
// warp tile 64x64 (4 m16 x 8 n8). cp.async double-buffered.
// =====================================================================
#define GTBM 256
#define GTBN 128
#define GTBK 32
#define GPAD 36
#define GABUF (GTBM * GPAD)      // 9216 floats
#define GWBUF (GTBN * GPAD)      // 4608 floats
#define GNK  (D_ / GTBK)         // 24
#define GEMM_SMEM ((2 * (GABUF + GWBUF)) * (int)sizeof(float))  // 110592 B

__global__ void __launch_bounds__(256, 1)
gemm_v4_kernel(const float* __restrict__ A, const float* __restrict__ W,
               const float* __restrict__ bias, const float* __restrict__ rope,
               float* __restrict__ C, int do_rope, int round_out)
{
    extern __shared__ float sm[];
    float* Abuf = sm;                    // [2][GABUF]
    float* Wbuf = sm + 2 * GABUF;        // [2][GWBUF]

    const int tid  = threadIdx.x;
    const int lane = tid & 31;
    const int warp = tid >> 5;
    const int wm   = (warp >> 1) * 64;   // 0,64,128,192
    const int wn   = (warp & 1)  * 64;   // 0,64
    const int bm   = blockIdx.y * GTBM;
    const int bn   = blockIdx.x * GTBN;
    const int g    = lane >> 2;
    const int t    = lane & 3;

    const float* Ap = A + (size_t)bm * D_;
    const float* Wp = W + (size_t)bn * D_;

    float acc[4][8][4];
#pragma unroll
    for (int mt = 0; mt < 4; mt++)
#pragma unroll
        for (int nt = 0; nt < 8; nt++)
#pragma unroll
            for (int r = 0; r < 4; r++) acc[mt][nt][r] = 0.0f;

    // ---- prologue: stage k-tile 0 ----
#pragma unroll
    for (int it = 0; it < 8; it++) {          // A: 256x32 = 2048 float4
        int f = tid + it * 256;
        int rr = f >> 3;
        int kk = (f & 7) * 4;
        cp_async16(&Abuf[rr * GPAD + kk], Ap + (size_t)rr * D_ + kk);
    }
#pragma unroll
    for (int it = 0; it < 4; it++) {          // W: 128x32 = 1024 float4
        int f = tid + it * 256;
        int rr = f >> 3;
        int kk = (f & 7) * 4;
        cp_async16(&Wbuf[rr * GPAD + kk], Wp + (size_t)rr * D_ + kk);
    }
    CP_COMMIT();

    for (int kt = 0; kt < GNK; kt++) {
        const int buf = kt & 1;
        if (kt + 1 < GNK) {
            const int k0n = (kt + 1) * GTBK;
            float* An = Abuf + (buf ^ 1) * GABUF;
            float* Wn = Wbuf + (buf ^ 1) * GWBUF;
#pragma unroll
            for (int it = 0; it < 8; it++) {
                int f = tid + it * 256;
                int rr = f >> 3;
                int kk = (f & 7) * 4;
                cp_async16(&An[rr * GPAD + kk], Ap + (size_t)rr * D_ + k0n + kk);
            }
#pragma unroll
            for (int it = 0; it < 4; it++) {
                int f = tid + it * 256;
                int rr = f >> 3;
                int kk = (f & 7) * 4;
                cp_async16(&Wn[rr * GPAD + kk], Wp + (size_t)rr * D_ + k0n + kk);
            }
        }
        CP_COMMIT();
        CP_WAIT1();
        __syncthreads();

        const float* Ab = Abuf + buf * GABUF;
        const float* Wb = Wbuf + buf * GWBUF;

#pragma unroll
        for (int kc = 0; kc < 4; kc++) {
            const int kk = kc * 8;
            uint32_t a[4][4];
#pragma unroll
            for (int mt = 0; mt < 4; mt++) {
                int r0 = wm + mt * 16 + g;
                a[mt][0] = __float_as_uint(Ab[(r0    ) * GPAD + kk + t    ]);
                a[mt][1] = __float_as_uint(Ab[(r0 + 8) * GPAD + kk + t    ]);
                a[mt][2] = __float_as_uint(Ab[(r0    ) * GPAD + kk + t + 4]);
                a[mt][3] = __float_as_uint(Ab[(r0 + 8) * GPAD + kk + t + 4]);
            }
#pragma unroll
            for (int nt = 0; nt < 8; nt++) {
                int n0 = wn + nt * 8 + g;
                uint32_t b0 = __float_as_uint(Wb[n0 * GPAD + kk + t    ]);
                uint32_t b1 = __float_as_uint(Wb[n0 * GPAD + kk + t + 4]);
#pragma unroll
                for (int mt = 0; mt < 4; mt++) {
                    asm volatile(
                        "mma.sync.aligned.m16n8k8.row.col.f32.tf32.tf32.f32 "
                        "{%0,%1,%2,%3}, {%4,%5,%6,%7}, {%8,%9}, {%0,%1,%2,%3};"
                        : "+f"(acc[mt][nt][0]), "+f"(acc[mt][nt][1]),
                          "+f"(acc[mt][nt][2]), "+f"(acc[mt][nt][3])
                        : "r"(a[mt][0]), "r"(a[mt][1]), "r"(a[mt][2]), "r"(a[mt][3]),
                          "r"(b0), "r"(b1));
                }
            }
        }
        __syncthreads();
    }

    // ---- epilogue: bias (+ RoPE) (+ tf32 round) + store ----
#pragma unroll
    for (int mt = 0; mt < 4; mt++) {
        int row0 = bm + wm + mt * 16 + g;
#pragma unroll
        for (int nt = 0; nt < 8; nt++) {
            int col = bn + wn + nt * 8 + t * 2;
            float2 bb = *(const float2*)(bias + col);
            float x0 = acc[mt][nt][0] + bb.x;
            float y0 = acc[mt][nt][1] + bb.y;
            float x1 = acc[mt][nt][2] + bb.x;
            float y1 = acc[mt][nt][3] + bb.y;
            if (do_rope) {
                int dh = col & (DH_ - 1);
                float2 a0 = *(const float2*)(rope + (size_t)row0 * DH_ + dh);
                float2 a1 = *(const float2*)(rope + (size_t)(row0 + 8) * DH_ + dh);
                float c0, s0, c1, s1;
                __sincosf(a0.x, &s0, &c0);
                __sincosf(a0.y, &s1, &c1);
                float nx0 = x0 * c0 - y0 * s0;
                float ny0 = y0 * c1 + x0 * s1;
                __sincosf(a1.x, &s0, &c0);
                __sincosf(a1.y, &s1, &c1);
                float nx1 = x1 * c0 - y1 * s0;
                float ny1 = y1 * c1 + x1 * s1;
                x0 = nx0; y0 = ny0; x1 = nx1; y1 = ny1;
            }
            if (round_out) {
                x0 = to_tf32(x0); y0 = to_tf32(y0);
                x1 = to_tf32(x1); y1 = to_tf32(y1);
            }
            *(float2*)(C + (size_t)row0 * D_ + col)       = make_float2(x0, y0);
            *(float2*)(C + (size_t)(row0 + 8) * D_ + col) = make_float2(x1, y1);
        }
    }
}

// =====================================================================
// Tensor-core flash attention v3 (unchanged from R11 passing version)
// =====================================================================
#define APAD 72
#define ABQ  128
#define NQT  ((S_ + ABQ - 1) / ABQ)   // 7
#define NKT  ((S_ + 63) / 64)         // 13
#define ATTN_SMEM ((ABQ + 64 + 64 + ABQ) * APAD * (int)sizeof(float))  // 110592

__global__ void __launch_bounds__(128)
attn_mma_kernel(const float* __restrict__ Q, const float* __restrict__ K,
                const float* __restrict__ V, float* __restrict__ O)
{
    extern __shared__ float smem[];
    float* Qs = smem;                   // [ABQ][APAD]
    float* Ks = Qs + ABQ * APAD;        // [64][APAD]
    float* Vs = Ks + 64 * APAD;         // [64][APAD]
    float* Ps = Vs + 64 * APAD;         // [ABQ][APAD]

    const int tid  = threadIdx.x;
    const int lane = tid & 31;
    const int warp = tid >> 5;
    const int g    = lane >> 2;
    const int t    = lane & 3;
    const int wr   = warp * 32;

    const int q0 = blockIdx.x * ABQ;
    const int h  = blockIdx.y;
    const int b  = blockIdx.z;

    const float* Qb = Q + (size_t)b * S_ * D_ + h * DH_;
    const float* Kb = K + (size_t)b * S_ * D_ + h * DH_;
    const float* Vb = V + (size_t)b * S_ * D_ + h * DH_;

#pragma unroll
    for (int i = 0; i < 16; i++) {
        int f = tid + i * 128;
        int r = f >> 4, c = (f & 15) * 4;
        int s = q0 + r; if (s >= S_) s = S_ - 1;
        cp_async16(&Qs[r * APAD + c], Qb + (size_t)s * D_ + c);
    }
#pragma unroll
    for (int i = 0; i < 8; i++) {
        int f = tid + i * 128;
        int r = f >> 4, c = (f & 15) * 4;
        int s = r; if (s >= S_) s = S_ - 1;
        cp_async16(&Ks[r * APAD + c], Kb + (size_t)s * D_ + c);
    }
    CP_COMMIT();
#pragma unroll
    for (int i = 0; i < 8; i++) {
        int f = tid + i * 128;
        int r = f >> 4, c = (f & 15) * 4;
        int s = r; if (s >= S_) s = S_ - 1;
        cp_async16(&Vs[r * APAD + c], Vb + (size_t)s * D_ + c);
    }
    CP_COMMIT();

    float o_acc[2][8][4];
#pragma unroll
    for (int mt = 0; mt < 2; mt++)
#pragma unroll
        for (int nt = 0; nt < 8; nt++)
#pragma unroll
            for (int r = 0; r < 4; r++) o_acc[mt][nt][r] = 0.f;
    float m_prev[2][2] = {{-1e30f, -1e30f}, {-1e30f, -1e30f}};
    float lsum[2][2]   = {{0.f, 0.f}, {0.f, 0.f}};

    const float scale = 0.125f;

    for (int kt = 0; kt < NKT; kt++) {
        const int k0 = kt * 64;

        CP_WAIT1();
        __syncthreads();

        float s_acc[2][8][4];
#pragma unroll
        for (int mt = 0; mt < 2; mt++)
#pragma unroll
            for (int nt = 0; nt < 8; nt++)
#pragma unroll
                for (int r = 0; r < 4; r++) s_acc[mt][nt][r] = 0.f;

#pragma unroll
        for (int kc = 0; kc < 8; kc++) {
            const int kk = kc * 8;
            uint32_t a[2][4];
#pragma unroll
            for (int mt = 0; mt < 2; mt++) {
                int r0 = wr + mt * 16 + g;
                a[mt][0] = __float_as_uint(Qs[(r0    ) * APAD + kk + t    ]);
                a[mt][1] = __float_as_uint(Qs[(r0 + 8) * APAD + kk + t    ]);
                a[mt][2] = __float_as_uint(Qs[(r0    ) * APAD + kk + t + 4]);
                a[mt][3] = __float_as_uint(Qs[(r0 + 8) * APAD + kk + t + 4]);
            }
#pragma unroll
            for (int nt = 0; nt < 8; nt++) {
                uint32_t b0 = __float_as_uint(Ks[(nt * 8 + g) * APAD + kk + t    ]);
                uint32_t b1 = __float_as_uint(Ks[(nt * 8 + g) * APAD + kk + t + 4]);
#pragma unroll
                for (int mt = 0; mt < 2; mt++) {
                    asm volatile(
                        "mma.sync.aligned.m16n8k8.row.col.f32.tf32.tf32.f32 "
                        "{%0,%1,%2,%3}, {%4,%5,%6,%7}, {%8,%9}, {%0,%1,%2,%3};"
                        : "+f"(s_acc[mt][nt][0]), "+f"(s_acc[mt][nt][1]),
                          "+f"(s_acc[mt][nt][2]), "+f"(s_acc[mt][nt][3])
                        : "r"(a[mt][0]), "r"(a[mt][1]), "r"(a[mt][2]), "r"(a[mt][3]),
                          "r"(b0), "r"(b1));
                }
            }
        }
        __syncthreads();

        if (kt + 1 < NKT) {
            const int kn = (kt + 1) * 64;
#pragma unroll
            for (int i = 0; i < 8; i++) {
                int f = tid + i * 128;
                int r = f >> 4, c = (f & 15) * 4;
                int s = kn + r; if (s >= S_) s = S_ - 1;
                cp_async16(&Ks[r * APAD + c], Kb + (size_t)s * D_ + c);
            }
        }
        CP_COMMIT();

#pragma unroll
        for (int mt = 0; mt < 2; mt++)
#pragma unroll
            for (int nt = 0; nt < 8; nt++) {
                int c0 = k0 + nt * 8 + 2 * t;
#pragma unroll
                for (int r = 0; r < 4; r++) {
                    int col = c0 + (r & 1);
                    s_acc[mt][nt][r] = (col < S_) ? s_acc[mt][nt][r] * scale : -1e30f;
                }
            }

#pragma unroll
        for (int mt = 0; mt < 2; mt++)
#pragma unroll
            for (int half = 0; half < 2; half++) {
                float mx = -1e30f;
#pragma unroll
                for (int nt = 0; nt < 8; nt++) {
                    mx = fmaxf(mx, s_acc[mt][nt][2 * half]);
                    mx = fmaxf(mx, s_acc[mt][nt][2 * half + 1]);
                }
                mx = fmaxf(mx, __shfl_xor_sync(0xffffffffu, mx, 1));
                mx = fmaxf(mx, __shfl_xor_sync(0xffffffffu, mx, 2));

                float mn   = fmaxf(m_prev[mt][half], mx);
                float corr = __expf(m_prev[mt][half] - mn);
                float rs   = 0.f;
#pragma unroll
                for (int nt = 0; nt < 8; nt++) {
                    float p0 = __expf(s_acc[mt][nt][2 * half]     - mn);
                    float p1 = __expf(s_acc[mt][nt][2 * half + 1] - mn);
                    s_acc[mt][nt][2 * half]     = p0;
                    s_acc[mt][nt][2 * half + 1] = p1;
                    rs += p0 + p1;
                }
                rs += __shfl_xor_sync(0xffffffffu, rs, 1);
                rs += __shfl_xor_sync(0xffffffffu, rs, 2);

                lsum[mt][half]   = lsum[mt][half] * corr + rs;
                m_prev[mt][half] = mn;
#pragma unroll
                for (int nt = 0; nt < 8; nt++) {
                    o_acc[mt][nt][2 * half]     *= corr;
                    o_acc[mt][nt][2 * half + 1] *= corr;
                }
            }

        CP_WAIT1();
        __syncthreads();

#pragma unroll
        for (int mt = 0; mt < 2; mt++)
#pragma unroll
            for (int nt = 0; nt < 8; nt++) {
                float2 p0, p1;
                p0.x = to_tf32(s_acc[mt][nt][0]);
                p0.y = to_tf32(s_acc[mt][nt][1]);
                p1.x = to_tf32(s_acc[mt][nt][2]);
                p1.y = to_tf32(s_acc[mt][nt][3]);
                *(float2*)&Ps[(wr + mt * 16 + g    ) * APAD + nt * 8 + 2 * t] = p0;
                *(float2*)&Ps[(wr + mt * 16 + g + 8) * APAD + nt * 8 + 2 * t] = p1;
            }
        __syncwarp();

#pragma unroll
        for (int kc = 0; kc < 8; kc++) {
            const int kk = kc * 8;
            uint32_t a[2][4];
#pragma unroll
            for (int mt = 0; mt < 2; mt++) {
                int r0 = wr + mt * 16 + g;
                a[mt][0] = __float_as_uint(Ps[(r0    ) * APAD + kk + t    ]);
                a[mt][1] = __float_as_uint(Ps[(r0 + 8) * APAD + kk + t    ]);
                a[mt][2] = __float_as_uint(Ps[(r0    ) * APAD + kk + t + 4]);
                a[mt][3] = __float_as_uint(Ps[(r0 + 8) * APAD + kk + t + 4]);
            }
#pragma unroll
            for (int nt = 0; nt < 8; nt++) {
                uint32_t b0 = __float_as_uint(Vs[(kk + t    ) * APAD + nt * 8 + g]);
                uint32_t b1 = __float_as_uint(Vs[(kk + t + 4) * APAD + nt * 8 + g]);
#pragma unroll
                for (int mt = 0; mt < 2; mt++) {
                    asm volatile(
                        "mma.sync.aligned.m16n8k8.row.col.f32.tf32.tf32.f32 "
                        "{%0,%1,%2,%3}, {%4,%5,%6,%7}, {%8,%9}, {%0,%1,%2,%3};"
                        : "+f"(o_acc[mt][nt][0]), "+f"(o_acc[mt][nt][1]),
                          "+f"(o_acc[mt][nt][2]), "+f"(o_acc[mt][nt][3])
                        : "r"(a[mt][0]), "r"(a[mt][1]), "r"(a[mt][2]), "r"(a[mt][3]),
                          "r"(b0), "r"(b1));
                }
            }
        }
        __syncthreads();

        if (kt + 1 < NKT) {
            const int kn = (kt + 1) * 64;
#pragma unroll
            for (int i = 0; i < 8; i++) {
                int f = tid + i * 128;
                int r = f >> 4, c = (f & 15) * 4;
                int s = kn + r; if (s >= S_) s = S_ - 1;
                cp_async16(&Vs[r * APAD + c], Vb + (size_t)s * D_ + c);
            }
        }
        CP_COMMIT();
    }

#pragma unroll
    for (int mt = 0; mt < 2; mt++) {
        float inv0 = 1.0f / lsum[mt][0];
        float inv1 = 1.0f / lsum[mt][1];
        int r0 = q0 + wr + mt * 16 + g;
        int r1 = r0 + 8;
#pragma unroll
        for (int nt = 0; nt < 8; nt++) {
            int col = h * DH_ + nt * 8 + 2 * t;
            if (r0 < S_) {
                float2 o;
                o.x = to_tf32(o_acc[mt][nt][0] * inv0);
                o.y = to_tf32(o_acc[mt][nt][1] * inv0);
                *(float2*)(O + ((size_t)b * S_ + r0) * D_ + col) = o;
            }
            if (r1 < S_) {
                float2 o;
                o.x = to_tf32(o_acc[mt][nt][2] * inv1);
                o.y = to_tf32(o_acc[mt][nt][3] * inv1);
                *(float2*)(O + ((size_t)b * S_ + r1) * D_ + col) = o;
            }
        }
    }
}

// ---------------- launch ----------------
extern "C" void kernel_launch(void* const* d_in, const int* in_sizes, int n_in,
                              void* d_out, int out_size)
{
    const float* hs   = (const float*)d_in[0];
    const float* rope = (const float*)d_in[1];
    const float* wq   = (const float*)d_in[2];
    const float* bq   = (const float*)d_in[3];
    const float* wk   = (const float*)d_in[4];
    const float* bk   = (const float*)d_in[5];
    const float* wv   = (const float*)d_in[6];
    const float* bv   = (const float*)d_in[7];
    const float* wo   = (const float*)d_in[8];
    const float* bo   = (const float*)d_in[9];
    float* out = (float*)d_out;

    float *gq, *gk, *gv, *gao, *gw;
    cudaGetSymbolAddress((void**)&gq,  g_q);
    cudaGetSymbolAddress((void**)&gk,  g_k);
    cudaGetSymbolAddress((void**)&gv,  g_v);
    cudaGetSymbolAddress((void**)&gao, g_ao);
    cudaGetSymbolAddress((void**)&gw,  g_w);

    cudaFuncSetAttribute(attn_mma_kernel,
                         cudaFuncAttributeMaxDynamicSharedMemorySize, ATTN_SMEM);
    cudaFuncSetAttribute(gemm_v4_kernel,
                         cudaFuncAttributeMaxDynamicSharedMemorySize, GEMM_SMEM);

    // ---- pre-round hs (1 launch) and all weights (1 launch) ----
    const int nhs4 = M_ * D_ / 4;
    const int nw4  = D_ * D_ / 4;
    round4_kernel<<<(nhs4 + 255) / 256, 256>>>(hs, gao, nhs4);
    round_w_kernel<<<(4 * nw4 + 255) / 256, 256>>>(wq, wk, wv, wo, gw, nw4);

    dim3 gblk(256);
    dim3 ggrid(D_ / GTBN, M_ / GTBM);   // (6, 49)

    gemm_v4_kernel<<<ggrid, gblk, GEMM_SMEM>>>(gao, gw + 0 * (size_t)D_ * D_, bq, rope, gq, 1, 1);
    gemm_v4_kernel<<<ggrid, gblk, GEMM_SMEM>>>(gao, gw + 1 * (size_t)D_ * D_, bk, rope, gk, 1, 1);
    gemm_v4_kernel<<<ggrid, gblk, GEMM_SMEM>>>(gao, gw + 2 * (size_t)D_ * D_, bv, rope, gv, 0, 1);

    dim3 agrid(NQT, H_, B_);            // (7, 12, 16)
    attn_mma_kernel<<<agrid, 128, ATTN_SMEM>>>(gq, gk, gv, gao);

    gemm_v4_kernel<<<ggrid, gblk, GEMM_SMEM>>>(gao, gw + 3 * (size_t)D_ * D_, bo, rope, out, 0, 0);
}

// round 17
// speedup vs baseline: 1.1452x; 1.0073x over previous
#include <cuda_runtime.h>
#include <math.h>
#include <stdint.h>

#define B_  16
#define S_  784
#define D_  768
#define H_  12
#define DH_ 64
#define M_  (B_ * S_)          // 12544

// ---------------- scratch (device globals: allocation-free) ----------------
__device__ float g_q [B_ * S_ * D_];
__device__ float g_k [B_ * S_ * D_];
__device__ float g_v [B_ * S_ * D_];
__device__ float g_ao[B_ * S_ * D_];     // rounded hs first, attention output later
__device__ float g_w [4 * D_ * D_];      // rounded weights

__device__ __forceinline__ float to_tf32(float x) {
    uint32_t u;
    asm("cvt.rna.tf32.f32 %0, %1;" : "=r"(u) : "f"(x));
    return __uint_as_float(u);
}

__device__ __forceinline__ void cp_async16(void* dst, const void* src) {
    uint32_t d = (uint32_t)__cvta_generic_to_shared(dst);
    asm volatile("cp.async.cg.shared.global [%0], [%1], 16;\n" :: "r"(d), "l"(src));
}
#define CP_COMMIT() asm volatile("cp.async.commit_group;\n" ::: "memory")
#define CP_WAIT1()  asm volatile("cp.async.wait_group 1;\n" ::: "memory")

// =====================================================================
// RNA tf32 pre-rounding
// =====================================================================
__global__ void __launch_bounds__(256)
round4_kernel(const float* __restrict__ in, float* __restrict__ out, int n4)
{
    int i = blockIdx.x * 256 + threadIdx.x;
    if (i < n4) {
        float4 v = ((const float4*)in)[i];
        float4 o;
        o.x = to_tf32(v.x);
        o.y = to_tf32(v.y);
        o.z = to_tf32(v.z);
        o.w = to_tf32(v.w);
        ((float4*)out)[i] = o;
    }
}

__global__ void __launch_bounds__(256)
round_w_kernel(const float* __restrict__ w0, const float* __restrict__ w1,
               const float* __restrict__ w2, const float* __restrict__ w3,
               float* __restrict__ out, int n4)
{
    int i = blockIdx.x * 256 + threadIdx.x;
    if (i < 4 * n4) {
        int sel = i / n4;
        int j   = i - sel * n4;
        const float* src = (sel == 0) ? w0 : (sel == 1) ? w1 : (sel == 2) ? w2 : w3;
        float4 v = ((const float4*)src)[j];
        float4 o;
        o.x = to_tf32(v.x);
        o.y = to_tf32(v.y);
        o.z = to_tf32(v.z);
        o.w = to_tf32(v.w);
        ((float4*)out)[i] = o;
    }
}

// =====================================================================
// GEMM body: C[M,N] = A[M,K] @ W[N,K]^T + bias (+RoPE) (+tf32 round)
// A and W PRE-ROUNDED tf32; raw bits feed the MMA.
// Block 128x128, K-tile 32, 8 warps (4m x 2n), warp tile 32x64.
// cp.async double-buffered. Designed for 2 CTAs/SM (128-reg budget).
// =====================================================================
#define GTBM 128
#define GTBN 128
#define GTBK 32
#define GPAD 36
#define GBUF (GTBM * GPAD)
#define GNK  (D_ / GTBK)
#define GEMM_SMEM (4 * GBUF * (int)sizeof(float))  // 73728 B

__device__ __forceinline__ void gemm_body(
    const float* __restrict__ A, const float* __restrict__ W,
    const float* __restrict__ bias, const float* __restrict__ rope,
    float* __restrict__ C, int do_rope, int round_out, float* sm)
{
    float* Abuf = sm;
    float* Wbuf = sm + 2 * GBUF;

    const int tid  = threadIdx.x;
    const int lane = tid & 31;
    const int warp = tid >> 5;
    const int wm   = (warp >> 1) * 32;
    const int wn   = (warp & 1)  * 64;
    const int bm   = blockIdx.y * GTBM;
    const int bn   = blockIdx.x * GTBN;
    const int g    = lane >> 2;
    const int t    = lane & 3;

    const float* Ap = A + (size_t)bm * D_;
    const float* Wp = W + (size_t)bn * D_;

    float acc[2][8][4];
#pragma unroll
    for (int mt = 0; mt < 2; mt++)
#pragma unroll
        for (int nt = 0; nt < 8; nt++)
#pragma unroll
            for (int r = 0; r < 4; r++) acc[mt][nt][r] = 0.0f;

#pragma unroll
    for (int it = 0; it < 4; it++) {
        int f = tid + it * 256;
        int rr = f >> 3;
        int kk = (f & 7) * 4;
        cp_async16(&Abuf[rr * GPAD + kk], Ap + (size_t)rr * D_ + kk);
    }
#pragma unroll
    for (int it = 0; it < 4; it++) {
        int f = tid + it * 256;
        int rr = f >> 3;
        int kk = (f & 7) * 4;
        cp_async16(&Wbuf[rr * GPAD + kk], Wp + (size_t)rr * D_ + kk);
    }
    CP_COMMIT();

    for (int kt = 0; kt < GNK; kt++) {
        const int buf = kt & 1;
        if (kt + 1 < GNK) {
            const int k0n = (kt + 1) * GTBK;
            float* An = Abuf + (buf ^ 1) * GBUF;
            float* Wn = Wbuf + (buf ^ 1) * GBUF;
#pragma unroll
            for (int it = 0; it < 4; it++) {
                int f = tid + it * 256;
                int rr = f >> 3;
                int kk = (f & 7) * 4;
                cp_async16(&An[rr * GPAD + kk], Ap + (size_t)rr * D_ + k0n + kk);
            }
#pragma unroll
            for (int it = 0; it < 4; it++) {
                int f = tid + it * 256;
                int rr = f >> 3;
                int kk = (f & 7) * 4;
                cp_async16(&Wn[rr * GPAD + kk], Wp + (size_t)rr * D_ + k0n + kk);
            }
        }
        CP_COMMIT();
        CP_WAIT1();
        __syncthreads();

        const float* Ab = Abuf + buf * GBUF;
        const float* Wb = Wbuf + buf * GBUF;

#pragma unroll
        for (int kc = 0; kc < 4; kc++) {
            const int kk = kc * 8;
            uint32_t a[2][4];
#pragma unroll
            for (int mt = 0; mt < 2; mt++) {
                int r0 = wm + mt * 16 + g;
                a[mt][0] = __float_as_uint(Ab[(r0    ) * GPAD + kk + t    ]);
                a[mt][1] = __float_as_uint(Ab[(r0 + 8) * GPAD + kk + t    ]);
                a[mt][2] = __float_as_uint(Ab[(r0    ) * GPAD + kk + t + 4]);
                a[mt][3] = __float_as_uint(Ab[(r0 + 8) * GPAD + kk + t + 4]);
            }
#pragma unroll
            for (int nt = 0; nt < 8; nt++) {
                int n0 = wn + nt * 8 + g;
                uint32_t b0 = __float_as_uint(Wb[n0 * GPAD + kk + t    ]);
                uint32_t b1 = __float_as_uint(Wb[n0 * GPAD + kk + t + 4]);
#pragma unroll
                for (int mt = 0; mt < 2; mt++) {
                    asm volatile(
                        "mma.sync.aligned.m16n8k8.row.col.f32.tf32.tf32.f32 "
                        "{%0,%1,%2,%3}, {%4,%5,%6,%7}, {%8,%9}, {%0,%1,%2,%3};"
                        : "+f"(acc[mt][nt][0]), "+f"(acc[mt][nt][1]),
                          "+f"(acc[mt][nt][2]), "+f"(acc[mt][nt][3])
                        : "r"(a[mt][0]), "r"(a[mt][1]), "r"(a[mt][2]), "r"(a[mt][3]),
                          "r"(b0), "r"(b1));
                }
            }
        }
        __syncthreads();
    }

    // ---- epilogue: bias (+ RoPE) (+ tf32 round) + store ----
#pragma unroll
    for (int mt = 0; mt < 2; mt++) {
        int row0 = bm + wm + mt * 16 + g;
#pragma unroll
        for (int nt = 0; nt < 8; nt++) {
            int col = bn + wn + nt * 8 + t * 2;
            float2 bb = *(const float2*)(bias + col);
            float x0 = acc[mt][nt][0] + bb.x;
            float y0 = acc[mt][nt][1] + bb.y;
            float x1 = acc[mt][nt][2] + bb.x;
            float y1 = acc[mt][nt][3] + bb.y;
            if (do_rope) {
                int dh = col & (DH_ - 1);
                float2 a0 = *(const float2*)(rope + (size_t)row0 * DH_ + dh);
                float2 a1 = *(const float2*)(rope + (size_t)(row0 + 8) * DH_ + dh);
                float c0, s0, c1, s1;
                __sincosf(a0.x, &s0, &c0);
                __sincosf(a0.y, &s1, &c1);
                float nx0 = x0 * c0 - y0 * s0;
                float ny0 = y0 * c1 + x0 * s1;
                __sincosf(a1.x, &s0, &c0);
                __sincosf(a1.y, &s1, &c1);
                float nx1 = x1 * c0 - y1 * s0;
                float ny1 = y1 * c1 + x1 * s1;
                x0 = nx0; y0 = ny0; x1 = nx1; y1 = ny1;
            }
            if (round_out) {
                x0 = to_tf32(x0); y0 = to_tf32(y0);
                x1 = to_tf32(x1); y1 = to_tf32(y1);
            }
            *(float2*)(C + (size_t)row0 * D_ + col)       = make_float2(x0, y0);
            *(float2*)(C + (size_t)(row0 + 8) * D_ + col) = make_float2(x1, y1);
        }
    }
}

// fused Q/K/V projection: blockIdx.z selects weight/bias/output
__global__ void __launch_bounds__(256, 2)
gemm_qkv_kernel(const float* __restrict__ A, const float* __restrict__ Wbase,
                const float* __restrict__ b0, const float* __restrict__ b1,
                const float* __restrict__ b2, const float* __restrict__ rope,
                float* __restrict__ C0, float* __restrict__ C1, float* __restrict__ C2)
{
    extern __shared__ float sm[];
    const int z = blockIdx.z;
    const float* W    = Wbase + (size_t)z * D_ * D_;
    const float* bias = (z == 0) ? b0 : (z == 1) ? b1 : b2;
    float*       C    = (z == 0) ? C0 : (z == 1) ? C1 : C2;
    gemm_body(A, W, bias, rope, C, (z < 2) ? 1 : 0, 1, sm);
}

// output projection
__global__ void __launch_bounds__(256, 2)
gemm_o_kernel(const float* __restrict__ A, const float* __restrict__ W,
              const float* __restrict__ bias, const float* __restrict__ rope,
              float* __restrict__ C)
{
    extern __shared__ float sm[];
    gemm_body(A, W, bias, rope, C, 0, 0, sm);
}

// =====================================================================
// Tensor-core flash attention (R11 passing version, verbatim)
// =====================================================================
#define APAD 72
#define ABQ  128
#define NQT  ((S_ + ABQ - 1) / ABQ)   // 7
#define NKT  ((S_ + 63) / 64)         // 13
#define ATTN_SMEM ((ABQ + 64 + 64 + ABQ) * APAD * (int)sizeof(float))  // 110592

__global__ void __launch_bounds__(128)
attn_mma_kernel(const float* __restrict__ Q, const float* __restrict__ K,
                const float* __restrict__ V, float* __restrict__ O)
{
    extern __shared__ float smem[];
    float* Qs = smem;                   // [ABQ][APAD]
    float* Ks = Qs + ABQ * APAD;        // [64][APAD]
    float* Vs = Ks + 64 * APAD;         // [64][APAD]
    float* Ps = Vs + 64 * APAD;         // [ABQ][APAD]

    const int tid  = threadIdx.x;
    const int lane = tid & 31;
    const int warp = tid >> 5;
    const int g    = lane >> 2;
    const int t    = lane & 3;
    const int wr   = warp * 32;

    const int q0 = blockIdx.x * ABQ;
    const int h  = blockIdx.y;
    const int b  = blockIdx.z;

    const float* Qb = Q + (size_t)b * S_ * D_ + h * DH_;
    const float* Kb = K + (size_t)b * S_ * D_ + h * DH_;
    const float* Vb = V + (size_t)b * S_ * D_ + h * DH_;

#pragma unroll
    for (int i = 0; i < 16; i++) {
        int f = tid + i * 128;
        int r = f >> 4, c = (f & 15) * 4;
        int s = q0 + r; if (s >= S_) s = S_ - 1;
        cp_async16(&Qs[r * APAD + c], Qb + (size_t)s * D_ + c);
    }
#pragma unroll
    for (int i = 0; i < 8; i++) {
        int f = tid + i * 128;
        int r = f >> 4, c = (f & 15) * 4;
        int s = r; if (s >= S_) s = S_ - 1;
        cp_async16(&Ks[r * APAD + c], Kb + (size_t)s * D_ + c);
    }
    CP_COMMIT();
#pragma unroll
    for (int i = 0; i < 8; i++) {
        int f = tid + i * 128;
        int r = f >> 4, c = (f & 15) * 4;
        int s = r; if (s >= S_) s = S_ - 1;
        cp_async16(&Vs[r * APAD + c], Vb + (size_t)s * D_ + c);
    }
    CP_COMMIT();

    float o_acc[2][8][4];
#pragma unroll
    for (int mt = 0; mt < 2; mt++)
#pragma unroll
        for (int nt = 0; nt < 8; nt++)
#pragma unroll
            for (int r = 0; r < 4; r++) o_acc[mt][nt][r] = 0.f;
    float m_prev[2][2] = {{-1e30f, -1e30f}, {-1e30f, -1e30f}};
    float lsum[2][2]   = {{0.f, 0.f}, {0.f, 0.f}};

    const float scale = 0.125f;

    for (int kt = 0; kt < NKT; kt++) {
        const int k0 = kt * 64;

        CP_WAIT1();
        __syncthreads();

        float s_acc[2][8][4];
#pragma unroll
        for (int mt = 0; mt < 2; mt++)
#pragma unroll
            for (int nt = 0; nt < 8; nt++)
#pragma unroll
                for (int r = 0; r < 4; r++) s_acc[mt][nt][r] = 0.f;

#pragma unroll
        for (int kc = 0; kc < 8; kc++) {
            const int kk = kc * 8;
            uint32_t a[2][4];
#pragma unroll
            for (int mt = 0; mt < 2; mt++) {
                int r0 = wr + mt * 16 + g;
                a[mt][0] = __float_as_uint(Qs[(r0    ) * APAD + kk + t    ]);
                a[mt][1] = __float_as_uint(Qs[(r0 + 8) * APAD + kk + t    ]);
                a[mt][2] = __float_as_uint(Qs[(r0    ) * APAD + kk + t + 4]);
                a[mt][3] = __float_as_uint(Qs[(r0 + 8) * APAD + kk + t + 4]);
            }
#pragma unroll
            for (int nt = 0; nt < 8; nt++) {
                uint32_t b0 = __float_as_uint(Ks[(nt * 8 + g) * APAD + kk + t    ]);
                uint32_t b1 = __float_as_uint(Ks[(nt * 8 + g) * APAD + kk + t + 4]);
#pragma unroll
                for (int mt = 0; mt < 2; mt++) {
                    asm volatile(
                        "mma.sync.aligned.m16n8k8.row.col.f32.tf32.tf32.f32 "
                        "{%0,%1,%2,%3}, {%4,%5,%6,%7}, {%8,%9}, {%0,%1,%2,%3};"
                        : "+f"(s_acc[mt][nt][0]), "+f"(s_acc[mt][nt][1]),
                          "+f"(s_acc[mt][nt][2]), "+f"(s_acc[mt][nt][3])
                        : "r"(a[mt][0]), "r"(a[mt][1]), "r"(a[mt][2]), "r"(a[mt][3]),
                          "r"(b0), "r"(b1));
                }
            }
        }
        __syncthreads();

        if (kt + 1 < NKT) {
            const int kn = (kt + 1) * 64;
#pragma unroll
            for (int i = 0; i < 8; i++) {
                int f = tid + i * 128;
                int r = f >> 4, c = (f & 15) * 4;
                int s = kn + r; if (s >= S_) s = S_ - 1;
                cp_async16(&Ks[r * APAD + c], Kb + (size_t)s * D_ + c);
            }
        }
        CP_COMMIT();

#pragma unroll
        for (int mt = 0; mt < 2; mt++)
#pragma unroll
            for (int nt = 0; nt < 8; nt++) {
                int c0 = k0 + nt * 8 + 2 * t;
#pragma unroll
                for (int r = 0; r < 4; r++) {
                    int col = c0 + (r & 1);
                    s_acc[mt][nt][r] = (col < S_) ? s_acc[mt][nt][r] * scale : -1e30f;
                }
            }

#pragma unroll
        for (int mt = 0; mt < 2; mt++)
#pragma unroll
            for (int half = 0; half < 2; half++) {
                float mx = -1e30f;
#pragma unroll
                for (int nt = 0; nt < 8; nt++) {
                    mx = fmaxf(mx, s_acc[mt][nt][2 * half]);
                    mx = fmaxf(mx, s_acc[mt][nt][2 * half + 1]);
                }
                mx = fmaxf(mx, __shfl_xor_sync(0xffffffffu, mx, 1));
                mx = fmaxf(mx, __shfl_xor_sync(0xffffffffu, mx, 2));

                float mn   = fmaxf(m_prev[mt][half], mx);
                float corr = __expf(m_prev[mt][half] - mn);
                float rs   = 0.f;
#pragma unroll
                for (int nt = 0; nt < 8; nt++) {
                    float p0 = __expf(s_acc[mt][nt][2 * half]     - mn);
                    float p1 = __expf(s_acc[mt][nt][2 * half + 1] - mn);
                    s_acc[mt][nt][2 * half]     = p0;
                    s_acc[mt][nt][2 * half + 1] = p1;
                    rs += p0 + p1;
                }
                rs += __shfl_xor_sync(0xffffffffu, rs, 1);
                rs += __shfl_xor_sync(0xffffffffu, rs, 2);

                lsum[mt][half]   = lsum[mt][half] * corr + rs;
                m_prev[mt][half] = mn;
#pragma unroll
                for (int nt = 0; nt < 8; nt++) {
                    o_acc[mt][nt][2 * half]     *= corr;
                    o_acc[mt][nt][2 * half + 1] *= corr;
                }
            }

        CP_WAIT1();
        __syncthreads();

#pragma unroll
        for (int mt = 0; mt < 2; mt++)
#pragma unroll
            for (int nt = 0; nt < 8; nt++) {
                float2 p0, p1;
                p0.x = to_tf32(s_acc[mt][nt][0]);
                p0.y = to_tf32(s_acc[mt][nt][1]);
                p1.x = to_tf32(s_acc[mt][nt][2]);
                p1.y = to_tf32(s_acc[mt][nt][3]);
                *(float2*)&Ps[(wr + mt * 16 + g    ) * APAD + nt * 8 + 2 * t] = p0;
                *(float2*)&Ps[(wr + mt * 16 + g + 8) * APAD + nt * 8 + 2 * t] = p1;
            }
        __syncwarp();

#pragma unroll
        for (int kc = 0; kc < 8; kc++) {
            const int kk = kc * 8;
            uint32_t a[2][4];
#pragma unroll
            for (int mt = 0; mt < 2; mt++) {
                int r0 = wr + mt * 16 + g;
                a[mt][0] = __float_as_uint(Ps[(r0    ) * APAD + kk + t    ]);
                a[mt][1] = __float_as_uint(Ps[(r0 + 8) * APAD + kk + t    ]);
                a[mt][2] = __float_as_uint(Ps[(r0    ) * APAD + kk + t + 4]);
                a[mt][3] = __float_as_uint(Ps[(r0 + 8) * APAD + kk + t + 4]);
            }
#pragma unroll
            for (int nt = 0; nt < 8; nt++) {
                uint32_t b0 = __float_as_uint(Vs[(kk + t    ) * APAD + nt * 8 + g]);
                uint32_t b1 = __float_as_uint(Vs[(kk + t + 4) * APAD + nt * 8 + g]);
#pragma unroll
                for (int mt = 0; mt < 2; mt++) {
                    asm volatile(
                        "mma.sync.aligned.m16n8k8.row.col.f32.tf32.tf32.f32 "
                        "{%0,%1,%2,%3}, {%4,%5,%6,%7}, {%8,%9}, {%0,%1,%2,%3};"
                        : "+f"(o_acc[mt][nt][0]), "+f"(o_acc[mt][nt][1]),
                          "+f"(o_acc[mt][nt][2]), "+f"(o_acc[mt][nt][3])
                        : "r"(a[mt][0]), "r"(a[mt][1]), "r"(a[mt][2]), "r"(a[mt][3]),
                          "r"(b0), "r"(b1));
                }
            }
        }
        __syncthreads();

        if (kt + 1 < NKT) {
            const int kn = (kt + 1) * 64;
#pragma unroll
            for (int i = 0; i < 8; i++) {
                int f = tid + i * 128;
                int r = f >> 4, c = (f & 15) * 4;
                int s = kn + r; if (s >= S_) s = S_ - 1;
                cp_async16(&Vs[r * APAD + c], Vb + (size_t)s * D_ + c);
            }
        }
        CP_COMMIT();
    }

#pragma unroll
    for (int mt = 0; mt < 2; mt++) {
        float inv0 = 1.0f / lsum[mt][0];
        float inv1 = 1.0f / lsum[mt][1];
        int r0 = q0 + wr + mt * 16 + g;
        int r1 = r0 + 8;
#pragma unroll
        for (int nt = 0; nt < 8; nt++) {
            int col = h * DH_ + nt * 8 + 2 * t;
            if (r0 < S_) {
                float2 o;
                o.x = to_tf32(o_acc[mt][nt][0] * inv0);
                o.y = to_tf32(o_acc[mt][nt][1] * inv0);
                *(float2*)(O + ((size_t)b * S_ + r0) * D_ + col) = o;
            }
            if (r1 < S_) {
                float2 o;
                o.x = to_tf32(o_acc[mt][nt][2] * inv1);
                o.y = to_tf32(o_acc[mt][nt][3] * inv1);
                *(float2*)(O + ((size_t)b * S_ + r1) * D_ + col) = o;
            }
        }
    }
}

// ---------------- launch ----------------
extern "C" void kernel_launch(void* const* d_in, const int* in_sizes, int n_in,
                              void* d_out, int out_size)
{
    const float* hs   = (const float*)d_in[0];
    const float* rope = (const float*)d_in[1];
    const float* wq   = (const float*)d_in[2];
    const float* bq   = (const float*)d_in[3];
    const float* wk   = (const float*)d_in[4];
    const float* bk   = (const float*)d_in[5];
    const float* wv   = (const float*)d_in[6];
    const float* bv   = (const float*)d_in[7];
    const float* wo   = (const float*)d_in[8];
    const float* bo   = (const float*)d_in[9];
    float* out = (float*)d_out;

    float *gq, *gk, *gv, *gao, *gw;
    cudaGetSymbolAddress((void**)&gq,  g_q);
    cudaGetSymbolAddress((void**)&gk,  g_k);
    cudaGetSymbolAddress((void**)&gv,  g_v);
    cudaGetSymbolAddress((void**)&gao, g_ao);
    cudaGetSymbolAddress((void**)&gw,  g_w);

    cudaFuncSetAttribute(attn_mma_kernel,
                         cudaFuncAttributeMaxDynamicSharedMemorySize, ATTN_SMEM);
    cudaFuncSetAttribute(gemm_qkv_kernel,
                         cudaFuncAttributeMaxDynamicSharedMemorySize, GEMM_SMEM);
    cudaFuncSetAttribute(gemm_o_kernel,
                         cudaFuncAttributeMaxDynamicSharedMemorySize, GEMM_SMEM);

    // ---- pre-round hs and all weights ----
    const int nhs4 = M_ * D_ / 4;
    const int nw4  = D_ * D_ / 4;
    round4_kernel<<<(nhs4 + 255) / 256, 256>>>(hs, gao, nhs4);
    round_w_kernel<<<(4 * nw4 + 255) / 256, 256>>>(wq, wk, wv, wo, gw, nw4);

    dim3 gblk(256);
    dim3 gqkv(D_ / GTBN, M_ / GTBM, 3);   // (6, 98, 3)
    gemm_qkv_kernel<<<gqkv, gblk, GEMM_SMEM>>>(gao, gw, bq, bk, bv, rope, gq, gk, gv);

    dim3 agrid(NQT, H_, B_);              // (7, 12, 16)
    attn_mma_kernel<<<agrid, 128, ATTN_SMEM>>>(gq, gk, gv, gao);

    dim3 go(D_ / GTBN, M_ / GTBM);        // (6, 98)
    gemm_o_kernel<<<go, gblk, GEMM_SMEM>>>(gao, gw + 3 * (size_t)D_ * D_, bo, rope, out);
}